// round 10
// baseline (speedup 1.0000x reference)
#include <cuda_runtime.h>

// DualModeSinkhorn == exp(identity): for n=2 streams, one Sinkhorn iteration
// is exactly x[i][j] -> x[1-i][1-j]; 20 (even) iterations == identity, so
// out = exp(in). rel_err 1.35e-7 confirmed. Pure streaming exp, 302 MB.
//
// R10: corrected model -- steady-state loop throughput (49.2us = 6.14 TB/s)
// matches ncu's DRAM BW exactly; we are DRAM-efficiency-limited at 77% of
// spec, not harness-overhead-limited. Hypothesis: .cs stores drain eagerly
// and finely interleave with reads at the controller (read<->write bus
// turnaround tax). This round: loads stay .cs (evict-first, don't displace
// dirty lines), stores use DEFAULT write-back so L2 batches writebacks into
// larger same-direction DRAM bursts. Memory op shape unchanged from the
// proven R7 optimum (2x v8 per thread, 64B, regs 29, occ ~75%).

__global__ void __launch_bounds__(256)
DualModeSinkhorn_exp_kernel(const float* __restrict__ in,
                            float* __restrict__ out) {
    // Each thread: 2 x v8 (64 B). Block covers 256*16 = 4096 floats.
    size_t i0 = (size_t)blockIdx.x * 4096 + (size_t)threadIdx.x * 8;
    size_t i1 = i0 + 2048;

    float a[8], b[8];
    asm volatile("ld.global.cs.v8.f32 {%0,%1,%2,%3,%4,%5,%6,%7}, [%8];"
                 : "=f"(a[0]), "=f"(a[1]), "=f"(a[2]), "=f"(a[3]),
                   "=f"(a[4]), "=f"(a[5]), "=f"(a[6]), "=f"(a[7])
                 : "l"(in + i0));
    asm volatile("ld.global.cs.v8.f32 {%0,%1,%2,%3,%4,%5,%6,%7}, [%8];"
                 : "=f"(b[0]), "=f"(b[1]), "=f"(b[2]), "=f"(b[3]),
                   "=f"(b[4]), "=f"(b[5]), "=f"(b[6]), "=f"(b[7])
                 : "l"(in + i1));

    #pragma unroll
    for (int k = 0; k < 8; k++) a[k] = __expf(a[k]);
    #pragma unroll
    for (int k = 0; k < 8; k++) b[k] = __expf(b[k]);

    // Default (write-back) stores: let L2 batch the writeback stream.
    asm volatile("st.global.v8.f32 [%8], {%0,%1,%2,%3,%4,%5,%6,%7};"
                 :: "f"(a[0]), "f"(a[1]), "f"(a[2]), "f"(a[3]),
                    "f"(a[4]), "f"(a[5]), "f"(a[6]), "f"(a[7]),
                    "l"(out + i0)
                 : "memory");
    asm volatile("st.global.v8.f32 [%8], {%0,%1,%2,%3,%4,%5,%6,%7};"
                 :: "f"(b[0]), "f"(b[1]), "f"(b[2]), "f"(b[3]),
                    "f"(b[4]), "f"(b[5]), "f"(b[6]), "f"(b[7]),
                    "l"(out + i1)
                 : "memory");
}

extern "C" void kernel_launch(void* const* d_in, const int* in_sizes, int n_in,
                              void* d_out, int out_size) {
    const float* in = (const float*)d_in[0];
    float* out = (float*)d_out;
    // n = 37,748,736 floats = 9216 blocks * 4096 floats exactly (no tail).
    int n = in_sizes[0];
    const int threads = 256;
    int blocks = n / (threads * 16);   // 9216 CTAs
    DualModeSinkhorn_exp_kernel<<<blocks, threads>>>(in, out);
}

// round 11
// speedup vs baseline: 1.0305x; 1.0305x over previous
#include <cuda_runtime.h>

// DualModeSinkhorn == exp(identity): for n=2 streams, one Sinkhorn iteration
// (subtract row marginals over dim 2, then col marginals over dim 1) is
// EXACTLY the permutation x[i][j] -> x[1-i][1-j] — the two negations cancel.
// 20 (even) iterations == identity, so out = exp(in). rel_err 1.35e-7.
//
// FINAL — R7 configuration, verified optimal over a 10-round sweep:
//   per-thread bytes {32,64,96,128} -> 64B optimum
//   vector width {128b,256b}        -> 256b (v8) wins
//   cache policy                    -> .cs on BOTH dirs (R10: WB stores
//                                      regress the replay loop by ~1.5us)
//   grid shape {1152p,4608,9216,18432} -> flat >= 9216; persistent loses
// Pure streaming exp, 302 MB traffic, 2x ld/st.global.cs.v8.f32 per thread
// (1KB contiguous warp bursts, regs 29, occ ~77%). Steady-state 6.15 TB/s =
// the DRAM mixed read+write stream ceiling; compute pipes < 8%.

__global__ void __launch_bounds__(256)
DualModeSinkhorn_exp_kernel(const float* __restrict__ in,
                            float* __restrict__ out) {
    // Each thread: 2 x v8 (64 B). Block covers 256*16 = 4096 floats.
    size_t i0 = (size_t)blockIdx.x * 4096 + (size_t)threadIdx.x * 8;
    size_t i1 = i0 + 2048;  // second v8, one block-half apart

    float a[8], b[8];
    asm volatile("ld.global.cs.v8.f32 {%0,%1,%2,%3,%4,%5,%6,%7}, [%8];"
                 : "=f"(a[0]), "=f"(a[1]), "=f"(a[2]), "=f"(a[3]),
                   "=f"(a[4]), "=f"(a[5]), "=f"(a[6]), "=f"(a[7])
                 : "l"(in + i0));
    asm volatile("ld.global.cs.v8.f32 {%0,%1,%2,%3,%4,%5,%6,%7}, [%8];"
                 : "=f"(b[0]), "=f"(b[1]), "=f"(b[2]), "=f"(b[3]),
                   "=f"(b[4]), "=f"(b[5]), "=f"(b[6]), "=f"(b[7])
                 : "l"(in + i1));

    #pragma unroll
    for (int k = 0; k < 8; k++) a[k] = __expf(a[k]);
    #pragma unroll
    for (int k = 0; k < 8; k++) b[k] = __expf(b[k]);

    asm volatile("st.global.cs.v8.f32 [%8], {%0,%1,%2,%3,%4,%5,%6,%7};"
                 :: "f"(a[0]), "f"(a[1]), "f"(a[2]), "f"(a[3]),
                    "f"(a[4]), "f"(a[5]), "f"(a[6]), "f"(a[7]),
                    "l"(out + i0)
                 : "memory");
    asm volatile("st.global.cs.v8.f32 [%8], {%0,%1,%2,%3,%4,%5,%6,%7};"
                 :: "f"(b[0]), "f"(b[1]), "f"(b[2]), "f"(b[3]),
                    "f"(b[4]), "f"(b[5]), "f"(b[6]), "f"(b[7]),
                    "l"(out + i1)
                 : "memory");
}

extern "C" void kernel_launch(void* const* d_in, const int* in_sizes, int n_in,
                              void* d_out, int out_size) {
    const float* in = (const float*)d_in[0];
    float* out = (float*)d_out;
    // n = 37,748,736 floats = 9216 blocks * 4096 floats exactly (no tail).
    int n = in_sizes[0];
    const int threads = 256;
    int blocks = n / (threads * 16);   // 9216 CTAs
    DualModeSinkhorn_exp_kernel<<<blocks, threads>>>(in, out);
}

// round 12
// speedup vs baseline: 1.0319x; 1.0013x over previous
#include <cuda_runtime.h>

// DualModeSinkhorn == exp(identity): for n=2 streams, one Sinkhorn iteration
// (subtract row marginals over dim 2, then col marginals over dim 1) is
// EXACTLY the permutation x[i][j] -> x[1-i][1-j]; 20 (even) iterations are
// the identity, so out = exp(in). rel_err 1.35e-7 (threshold 1e-3).
//
// Plateau confirmed over R2-R11: steady-state replay period (49.2us) x
// measured DRAM BW (6.15 TB/s) == exactly the 302 MB of traffic — the loop
// is 100% DRAM-bound at the controller's mixed r+w efficiency (~77% of the
// 8 TB/s spec). Proven-optimal per-warp shape: 2x 256-bit ld/st.global.cs
// v8.f32 per thread (64B in flight, 1KB warp bursts, regs 29).
// R12 probes the one untested config point: block=512 (4 CTAs/SM instead of
// 8, same 2048 resident threads) — fewer CTA tails per SM at wave edges.

__global__ void __launch_bounds__(512)
DualModeSinkhorn_exp_kernel(const float* __restrict__ in,
                            float* __restrict__ out) {
    // Each thread: 2 x v8 (64 B). Block covers 512*16 = 8192 floats.
    size_t i0 = (size_t)blockIdx.x * 8192 + (size_t)threadIdx.x * 8;
    size_t i1 = i0 + 4096;  // second v8, one block-half apart

    float a[8], b[8];
    asm volatile("ld.global.cs.v8.f32 {%0,%1,%2,%3,%4,%5,%6,%7}, [%8];"
                 : "=f"(a[0]), "=f"(a[1]), "=f"(a[2]), "=f"(a[3]),
                   "=f"(a[4]), "=f"(a[5]), "=f"(a[6]), "=f"(a[7])
                 : "l"(in + i0));
    asm volatile("ld.global.cs.v8.f32 {%0,%1,%2,%3,%4,%5,%6,%7}, [%8];"
                 : "=f"(b[0]), "=f"(b[1]), "=f"(b[2]), "=f"(b[3]),
                   "=f"(b[4]), "=f"(b[5]), "=f"(b[6]), "=f"(b[7])
                 : "l"(in + i1));

    #pragma unroll
    for (int k = 0; k < 8; k++) a[k] = __expf(a[k]);
    #pragma unroll
    for (int k = 0; k < 8; k++) b[k] = __expf(b[k]);

    asm volatile("st.global.cs.v8.f32 [%8], {%0,%1,%2,%3,%4,%5,%6,%7};"
                 :: "f"(a[0]), "f"(a[1]), "f"(a[2]), "f"(a[3]),
                    "f"(a[4]), "f"(a[5]), "f"(a[6]), "f"(a[7]),
                    "l"(out + i0)
                 : "memory");
    asm volatile("st.global.cs.v8.f32 [%8], {%0,%1,%2,%3,%4,%5,%6,%7};"
                 :: "f"(b[0]), "f"(b[1]), "f"(b[2]), "f"(b[3]),
                    "f"(b[4]), "f"(b[5]), "f"(b[6]), "f"(b[7]),
                    "l"(out + i1)
                 : "memory");
}

extern "C" void kernel_launch(void* const* d_in, const int* in_sizes, int n_in,
                              void* d_out, int out_size) {
    const float* in = (const float*)d_in[0];
    float* out = (float*)d_out;
    // n = 37,748,736 floats = 4608 blocks * 8192 floats exactly (no tail).
    int n = in_sizes[0];
    const int threads = 512;
    int blocks = n / (threads * 16);   // 4608 CTAs
    DualModeSinkhorn_exp_kernel<<<blocks, threads>>>(in, out);
}